// round 1
// baseline (speedup 1.0000x reference)
#include <cuda_runtime.h>

// ---------------------------------------------------------------------------
// Attention3D: x(2,8,16,16,768) -> qkv -> 12-head attention with decomposed
// rel-pos bias -> proj.  B*nh = 24 head-batches, N = 2048 tokens, hd = 64.
// All fp32.  4 kernels: qkv gemm (scatter epilogue), rel-pos precompute,
// fused flash attention (online softmax, bias on the fly), proj gemm.
// ---------------------------------------------------------------------------

#define NHB   24      // B * num_heads
#define NSEQ  2048    // D*H*W
#define HD    64
#define CDIM  768
#define MROWS 4096    // B * N

// Scratch (no cudaMalloc allowed) -------------------------------------------
__device__ float g_q[NHB * NSEQ * HD];
__device__ float g_k[NHB * NSEQ * HD];
__device__ float g_v[NHB * NSEQ * HD];
__device__ float g_reld[NHB * NSEQ * 8];
__device__ float g_relh[NHB * NSEQ * 16];
__device__ float g_relw[NHB * NSEQ * 16];
__device__ float g_attnout[MROWS * CDIM];

// ---------------------------------------------------------------------------
// QKV GEMM:  (4096 x 768) @ (768 x 2304) + bias, scattered to g_q/g_k/g_v
// laid out as [hb][n][c]  (hb = b*12 + head).
// Tiling: 64x64 block, K-step 16, 256 threads, 4x4 micro-tile.
// ---------------------------------------------------------------------------
__global__ void __launch_bounds__(256) qkv_gemm_kernel(
    const float* __restrict__ x, const float* __restrict__ w,
    const float* __restrict__ bias)
{
    __shared__ float As[16][64];   // A transposed: As[k][m]
    __shared__ float Bs[16][64];   // Bs[k][n]
    const int bm = blockIdx.x * 64;
    const int bn = blockIdx.y * 64;
    const int tid = threadIdx.x;
    const int tx = tid & 15, ty = tid >> 4;
    const int ka = tid & 15, ma = (tid >> 4) << 2;
    const int nb = tid & 63, kb = tid >> 6;
    float acc[4][4] = {};

    for (int k0 = 0; k0 < 768; k0 += 16) {
#pragma unroll
        for (int i = 0; i < 4; i++)
            As[ka][ma + i] = x[(bm + ma + i) * 768 + k0 + ka];
#pragma unroll
        for (int i = 0; i < 4; i++)
            Bs[kb + i * 4][nb] = w[(k0 + kb + i * 4) * 2304 + bn + nb];
        __syncthreads();
#pragma unroll
        for (int kk = 0; kk < 16; kk++) {
            float4 a4 = *(const float4*)&As[kk][ty << 2];
            float4 b4 = *(const float4*)&Bs[kk][tx << 2];
            float av[4] = {a4.x, a4.y, a4.z, a4.w};
            float bv[4] = {b4.x, b4.y, b4.z, b4.w};
#pragma unroll
            for (int ii = 0; ii < 4; ii++)
#pragma unroll
                for (int jj = 0; jj < 4; jj++)
                    acc[ii][jj] += av[ii] * bv[jj];
        }
        __syncthreads();
    }

#pragma unroll
    for (int ii = 0; ii < 4; ii++) {
        const int mrow = bm + (ty << 2) + ii;
        const int b = mrow >> 11, n = mrow & 2047;
#pragma unroll
        for (int jj = 0; jj < 4; jj++) {
            const int j = bn + (tx << 2) + jj;
            const float val = acc[ii][jj] + bias[j];
            const int which = j / 768;
            const int head = (j % 768) >> 6;
            const int c = j & 63;
            float* dst = (which == 0) ? g_q : (which == 1) ? g_k : g_v;
            dst[((b * 12 + head) * NSEQ + n) * HD + c] = val;
        }
    }
}

// ---------------------------------------------------------------------------
// Rel-pos bias tables: rel_d[hb][n][kd] = q[hb][n] . rel_pos_d[d(n)-kd+7]
// (and likewise h with +15, w with +15).  One thread per output scalar.
// ---------------------------------------------------------------------------
__global__ void __launch_bounds__(256) relpos_kernel(
    const float* __restrict__ rpd, const float* __restrict__ rph,
    const float* __restrict__ rpw)
{
    const int idx = blockIdx.x * 256 + threadIdx.x;   // NHB*NSEQ*40 total
    if (idx >= NHB * NSEQ * 40) return;
    const int j  = idx % 40;
    const int n  = (idx / 40) % NSEQ;
    const int hb = idx / (40 * NSEQ);
    const float* qrow = &g_q[(hb * NSEQ + n) * HD];
    const int d = n >> 8, h = (n >> 4) & 15, wq = n & 15;

    const float* trow;
    float* dst;
    if (j < 8) {
        trow = &rpd[(d - j + 7) * HD];
        dst  = &g_reld[(hb * NSEQ + n) * 8 + j];
    } else if (j < 24) {
        const int kh = j - 8;
        trow = &rph[(h - kh + 15) * HD];
        dst  = &g_relh[(hb * NSEQ + n) * 16 + kh];
    } else {
        const int kw = j - 24;
        trow = &rpw[(wq - kw + 15) * HD];
        dst  = &g_relw[(hb * NSEQ + n) * 16 + kw];
    }
    float s = 0.f;
#pragma unroll
    for (int c = 0; c < HD; c++) s += qrow[c] * trow[c];
    *dst = s;
}

// ---------------------------------------------------------------------------
// Fused flash attention with decomposed bias.
// Block = (q-tile of 64, head-batch).  256 threads (16x16), 4x4 micro-tiles.
// Dynamic smem layout (floats):
//   Qt [64][68]  (c-major, padded)   @ 0      (4352)
//   Kt [64][68]                      @ 4352   (4352)
//   Vs [64][64]  (k-major)           @ 8704   (4096)
//   Ps [64][64]  (q-major)           @ 12800  (4096)
//   rD [64][8]                       @ 16896  (512)
//   rH [64][16]                      @ 17408  (1024)
//   rW [64][16]                      @ 18432  (1024)   total 19456 fl = 77824 B
// ---------------------------------------------------------------------------
#define FL_SMEM_FLOATS 19456
#define FL_SMEM_BYTES  (FL_SMEM_FLOATS * 4)

__global__ void __launch_bounds__(256) flash_kernel()
{
    extern __shared__ float sm[];
    float* Qt = sm;
    float* Kt = sm + 4352;
    float* Vs = sm + 8704;
    float* Ps = sm + 12800;
    float* rD = sm + 16896;
    float* rH = sm + 17408;
    float* rW = sm + 18432;

    const int qt = blockIdx.x;          // 0..31
    const int hb = blockIdx.y;          // 0..23
    const int tid = threadIdx.x;
    const int tx = tid & 15, ty = tid >> 4;
    const int qbase = qt * 64;
    const float scale = 0.125f;         // hd^-0.5

    // --- load Q tile transposed (pitch 68) ---
    const float* Qg = &g_q[(hb * NSEQ + qbase) * HD];
#pragma unroll
    for (int it = 0; it < 4; it++) {
        const int f = it * 1024 + tid * 4;
        const int r = f >> 6, c0 = f & 63;
        float4 v = *(const float4*)&Qg[f];
        Qt[(c0 + 0) * 68 + r] = v.x;
        Qt[(c0 + 1) * 68 + r] = v.y;
        Qt[(c0 + 2) * 68 + r] = v.z;
        Qt[(c0 + 3) * 68 + r] = v.w;
    }
    // --- rel bias tables for these 64 queries (contiguous in global) ---
    for (int i = tid; i < 64 * 8; i += 256)
        rD[i] = g_reld[(hb * NSEQ + qbase) * 8 + i];
    for (int i = tid; i < 64 * 16; i += 256)
        rH[i] = g_relh[(hb * NSEQ + qbase) * 16 + i];
    for (int i = tid; i < 64 * 16; i += 256)
        rW[i] = g_relw[(hb * NSEQ + qbase) * 16 + i];

    float m[4], l[4], o[4][4];
#pragma unroll
    for (int ii = 0; ii < 4; ii++) {
        m[ii] = -1e30f; l[ii] = 0.f;
#pragma unroll
        for (int jj = 0; jj < 4; jj++) o[ii][jj] = 0.f;
    }

    for (int kt = 0; kt < 32; kt++) {
        __syncthreads();   // Q/rel ready (kt=0); prev O-update done with Ps/Vs
        const float* Kg = &g_k[(hb * NSEQ + kt * 64) * HD];
        const float* Vg = &g_v[(hb * NSEQ + kt * 64) * HD];
#pragma unroll
        for (int it = 0; it < 4; it++) {
            const int f = it * 1024 + tid * 4;
            const int r = f >> 6, c0 = f & 63;
            float4 kv = *(const float4*)&Kg[f];
            Kt[(c0 + 0) * 68 + r] = kv.x;
            Kt[(c0 + 1) * 68 + r] = kv.y;
            Kt[(c0 + 2) * 68 + r] = kv.z;
            Kt[(c0 + 3) * 68 + r] = kv.w;
            *(float4*)&Vs[f] = *(const float4*)&Vg[f];
        }
        __syncthreads();

        // --- S = Q K^T (64x64 over c=64) ---
        float s[4][4] = {};
#pragma unroll 8
        for (int c = 0; c < 64; c++) {
            float4 a4 = *(const float4*)&Qt[c * 68 + (ty << 2)];
            float4 b4 = *(const float4*)&Kt[c * 68 + (tx << 2)];
            float av[4] = {a4.x, a4.y, a4.z, a4.w};
            float bv[4] = {b4.x, b4.y, b4.z, b4.w};
#pragma unroll
            for (int ii = 0; ii < 4; ii++)
#pragma unroll
                for (int jj = 0; jj < 4; jj++)
                    s[ii][jj] += av[ii] * bv[jj];
        }

        // --- scale + decomposed rel-pos bias ---
        const int kd = kt >> 2;   // constant within a 64-key tile
#pragma unroll
        for (int ii = 0; ii < 4; ii++) {
            const int qr = (ty << 2) + ii;
            const float bd = rD[qr * 8 + kd];
#pragma unroll
            for (int jj = 0; jj < 4; jj++) {
                const int off = (tx << 2) + jj;
                const int kg = (kt << 6) + off;
                const int kh = (kg >> 4) & 15;
                const int kw = kg & 15;
                s[ii][jj] = s[ii][jj] * scale + bd + rH[qr * 16 + kh] + rW[qr * 16 + kw];
            }
        }

        // --- online softmax (row groups of 16 lanes share a q-row) ---
#pragma unroll
        for (int ii = 0; ii < 4; ii++) {
            float rmax = fmaxf(fmaxf(s[ii][0], s[ii][1]), fmaxf(s[ii][2], s[ii][3]));
#pragma unroll
            for (int off = 8; off >= 1; off >>= 1)
                rmax = fmaxf(rmax, __shfl_xor_sync(0xffffffffu, rmax, off));
            const float mn = fmaxf(m[ii], rmax);
            const float corr = __expf(m[ii] - mn);
            m[ii] = mn;
            float rs = 0.f;
#pragma unroll
            for (int jj = 0; jj < 4; jj++) {
                s[ii][jj] = __expf(s[ii][jj] - mn);
                rs += s[ii][jj];
            }
#pragma unroll
            for (int off = 8; off >= 1; off >>= 1)
                rs += __shfl_xor_sync(0xffffffffu, rs, off);
            l[ii] = l[ii] * corr + rs;
#pragma unroll
            for (int jj = 0; jj < 4; jj++) o[ii][jj] *= corr;
            *(float4*)&Ps[((ty << 2) + ii) * 64 + (tx << 2)] =
                make_float4(s[ii][0], s[ii][1], s[ii][2], s[ii][3]);
        }
        __syncthreads();

        // --- O += P V ---
#pragma unroll 4
        for (int k = 0; k < 64; k++) {
            float4 vv = *(const float4*)&Vs[k * 64 + (tx << 2)];
#pragma unroll
            for (int ii = 0; ii < 4; ii++) {
                const float p = Ps[((ty << 2) + ii) * 64 + k];
                o[ii][0] += p * vv.x;
                o[ii][1] += p * vv.y;
                o[ii][2] += p * vv.z;
                o[ii][3] += p * vv.w;
            }
        }
    }

    // --- finalize: O /= l, write interleaved (B,N, head*64+c) for proj ---
    const int b = hb / 12, head = hb % 12;
#pragma unroll
    for (int ii = 0; ii < 4; ii++) {
        const float inv = 1.0f / l[ii];
        const int qg = qbase + (ty << 2) + ii;
        float4 ov = make_float4(o[ii][0] * inv, o[ii][1] * inv,
                                o[ii][2] * inv, o[ii][3] * inv);
        *(float4*)&g_attnout[(b * NSEQ + qg) * CDIM + head * 64 + (tx << 2)] = ov;
    }
}

// ---------------------------------------------------------------------------
// Proj GEMM: (4096 x 768) @ (768 x 768) + bias -> d_out (row-major, matches
// (B,D,H,W,C)).
// ---------------------------------------------------------------------------
__global__ void __launch_bounds__(256) proj_gemm_kernel(
    const float* __restrict__ w, const float* __restrict__ bias,
    float* __restrict__ out)
{
    __shared__ float As[16][64];
    __shared__ float Bs[16][64];
    const int bm = blockIdx.x * 64;
    const int bn = blockIdx.y * 64;
    const int tid = threadIdx.x;
    const int tx = tid & 15, ty = tid >> 4;
    const int ka = tid & 15, ma = (tid >> 4) << 2;
    const int nb = tid & 63, kb = tid >> 6;
    float acc[4][4] = {};

    for (int k0 = 0; k0 < 768; k0 += 16) {
#pragma unroll
        for (int i = 0; i < 4; i++)
            As[ka][ma + i] = g_attnout[(bm + ma + i) * 768 + k0 + ka];
#pragma unroll
        for (int i = 0; i < 4; i++)
            Bs[kb + i * 4][nb] = w[(k0 + kb + i * 4) * 768 + bn + nb];
        __syncthreads();
#pragma unroll
        for (int kk = 0; kk < 16; kk++) {
            float4 a4 = *(const float4*)&As[kk][ty << 2];
            float4 b4 = *(const float4*)&Bs[kk][tx << 2];
            float av[4] = {a4.x, a4.y, a4.z, a4.w};
            float bv[4] = {b4.x, b4.y, b4.z, b4.w};
#pragma unroll
            for (int ii = 0; ii < 4; ii++)
#pragma unroll
                for (int jj = 0; jj < 4; jj++)
                    acc[ii][jj] += av[ii] * bv[jj];
        }
        __syncthreads();
    }

#pragma unroll
    for (int ii = 0; ii < 4; ii++) {
        const int mrow = bm + (ty << 2) + ii;
#pragma unroll
        for (int jj = 0; jj < 4; jj++) {
            const int j = bn + (tx << 2) + jj;
            out[mrow * 768 + j] = acc[ii][jj] + bias[j];
        }
    }
}

// ---------------------------------------------------------------------------
extern "C" void kernel_launch(void* const* d_in, const int* in_sizes, int n_in,
                              void* d_out, int out_size)
{
    const float* x      = (const float*)d_in[0];
    const float* qkv_w  = (const float*)d_in[1];
    const float* qkv_b  = (const float*)d_in[2];
    const float* proj_w = (const float*)d_in[3];
    const float* proj_b = (const float*)d_in[4];
    const float* rpd    = (const float*)d_in[5];
    const float* rph    = (const float*)d_in[6];
    const float* rpw    = (const float*)d_in[7];
    float* out = (float*)d_out;

    cudaFuncSetAttribute(flash_kernel,
                         cudaFuncAttributeMaxDynamicSharedMemorySize,
                         FL_SMEM_BYTES);

    qkv_gemm_kernel<<<dim3(64, 36), 256>>>(x, qkv_w, qkv_b);
    relpos_kernel<<<(NHB * NSEQ * 40 + 255) / 256, 256>>>(rpd, rph, rpw);
    flash_kernel<<<dim3(32, NHB), 256, FL_SMEM_BYTES>>>();
    proj_gemm_kernel<<<dim3(64, 12), 256>>>(proj_w, proj_b, out);
}